// round 1
// baseline (speedup 1.0000x reference)
#include <cuda_runtime.h>
#include <math.h>

// ---------------- scratch layout (single __device__ arena, no allocs) ----------------
constexpr size_t OFF_T1     = 0;                       // 64*4096
constexpr size_t OFF_HID    = OFF_T1     + 262144;     // 64*1024
constexpr size_t OFF_T2     = OFF_HID    + 65536;      // 64*4096
constexpr size_t OFF_AUTO   = OFF_T2     + 262144;     // 64*12288
constexpr size_t OFF_NEWX   = OFF_AUTO   + 786432;     // 128*24*512
constexpr size_t OFF_M1     = OFF_NEWX   + 1572864;    // 3072*512
constexpr size_t OFF_H1     = OFF_M1     + 1572864;    // 3072*512
constexpr size_t OFF_M2     = OFF_H1     + 1572864;    // 3072*512
constexpr size_t OFF_OUT1   = OFF_M2     + 1572864;    // 3072*256
constexpr size_t OFF_LSTMIN = OFF_OUT1   + 786432;     // 64*24*512
constexpr size_t OFF_XG     = OFF_LSTMIN + 786432;     // 1536*2048
constexpr size_t OFF_HSEQ0  = OFF_XG     + 3145728;    // 64*24*512
constexpr size_t OFF_HSEQ1  = OFF_HSEQ0  + 786432;     // 64*24*512
constexpr size_t OFF_HA     = OFF_HSEQ1  + 786432;     // 64*512
constexpr size_t OFF_HB     = OFF_HA     + 32768;      // 64*512
constexpr size_t OFF_C      = OFF_HB     + 32768;      // 64*512
constexpr size_t OFF_NF     = OFF_C      + 32768;      // 64*2560
constexpr size_t OFF_B0     = OFF_NF     + 163840;     // 2048
constexpr size_t OFF_B1     = OFF_B0     + 2048;       // 2048
constexpr size_t OFF_GP     = OFF_B1     + 2048;       // split-K partials, 524288
constexpr size_t TOTAL_SCRATCH = OFF_GP  + 524288;

__device__ float g_scratch[TOTAL_SCRATCH];

__device__ __forceinline__ float sigmoidf_(float v) { return 1.0f / (1.0f + expf(-v)); }

// ---------------- generic GEMM: C = act(A[M,K] * W[N,K]^T + bias) ----------------
// 64x64 tile, BK=16, 256 threads, 4x4 per thread. Optional split-K via gridDim.z:
// when kchunks > 1, raw partials are written to C + z*M*N (bias/relu deferred).
__global__ __launch_bounds__(256) void gemm64(
    const float* __restrict__ A, const float* __restrict__ W,
    const float* __restrict__ bias, float* __restrict__ C,
    int M, int N, int K, int kchunks, int relu)
{
    __shared__ float As[16][64];
    __shared__ float Ws[16][64];
    const int bm = blockIdx.y * 64;
    const int bn = blockIdx.x * 64;
    const int z  = blockIdx.z;
    const int Kc = K / kchunks;
    const int tid = threadIdx.x;
    const int tx = tid & 15, ty = tid >> 4;
    const int lr = tid >> 2, lc = (tid & 3) << 2;

    float acc[4][4];
#pragma unroll
    for (int i = 0; i < 4; i++)
#pragma unroll
        for (int j = 0; j < 4; j++) acc[i][j] = 0.0f;

    const float* Ap = A + (size_t)(bm + lr) * K + (size_t)z * Kc + lc;
    const float* Wp = W + (size_t)(bn + lr) * K + (size_t)z * Kc + lc;

    for (int kt = 0; kt < Kc; kt += 16) {
        float4 a4 = *(const float4*)(Ap + kt);
        float4 w4 = *(const float4*)(Wp + kt);
        As[lc + 0][lr] = a4.x; As[lc + 1][lr] = a4.y; As[lc + 2][lr] = a4.z; As[lc + 3][lr] = a4.w;
        Ws[lc + 0][lr] = w4.x; Ws[lc + 1][lr] = w4.y; Ws[lc + 2][lr] = w4.z; Ws[lc + 3][lr] = w4.w;
        __syncthreads();
#pragma unroll
        for (int kk = 0; kk < 16; kk++) {
            float4 av = *(const float4*)(&As[kk][ty << 2]);
            float4 wv = *(const float4*)(&Ws[kk][tx << 2]);
            float ar[4] = {av.x, av.y, av.z, av.w};
            float wr[4] = {wv.x, wv.y, wv.z, wv.w};
#pragma unroll
            for (int i = 0; i < 4; i++)
#pragma unroll
                for (int j = 0; j < 4; j++) acc[i][j] += ar[i] * wr[j];
        }
        __syncthreads();
    }

    if (kchunks == 1) {
#pragma unroll
        for (int i = 0; i < 4; i++) {
            int m = bm + (ty << 2) + i;
            float4 v;
            float* vp = (float*)&v;
#pragma unroll
            for (int j = 0; j < 4; j++) {
                int n = bn + (tx << 2) + j;
                float t = acc[i][j];
                if (bias) t += bias[n];
                if (relu) t = fmaxf(t, 0.0f);
                vp[j] = t;
            }
            *(float4*)(C + (size_t)m * N + bn + (tx << 2)) = v;
        }
    } else {
        float* Cz = C + (size_t)z * M * N;
#pragma unroll
        for (int i = 0; i < 4; i++) {
            int m = bm + (ty << 2) + i;
            float4 v = make_float4(acc[i][0], acc[i][1], acc[i][2], acc[i][3]);
            *(float4*)(Cz + (size_t)m * N + bn + (tx << 2)) = v;
        }
    }
}

// sum split-K partials + bias + optional relu
__global__ void reduce_bias_act(const float* __restrict__ GP, const float* __restrict__ bias,
                                float* __restrict__ out, int total, int N, int kchunks, int relu)
{
    int i = blockIdx.x * blockDim.x + threadIdx.x;
    if (i >= total) return;
    float s = 0.0f;
    for (int z = 0; z < kchunks; z++) s += GP[(size_t)z * total + i];
    if (bias) s += bias[i % N];
    if (relu) s = fmaxf(s, 0.0f);
    out[i] = s;
}

// autooutput -> d_out region; new_x = concat(x, x - auto) along batch
__global__ void ae_post(const float* __restrict__ x, const float* __restrict__ AUTO,
                        float* __restrict__ NEWX, float* __restrict__ outAuto)
{
    int i = blockIdx.x * blockDim.x + threadIdx.x;
    if (i >= 786432) return;
    float xv = x[i], av = AUTO[i];
    NEWX[i] = xv;
    NEWX[786432 + i] = xv - av;
    outAuto[i] = av;
}

// lstm_in flat [64,24,512] from OUT1 [(bfull,s) rows, 256 cols] via [S,2B,G2] C-order view
__global__ void permute_lstm_in(const float* __restrict__ OUT1, float* __restrict__ LSTMIN)
{
    int f = blockIdx.x * blockDim.x + threadIdx.x;
    if (f >= 786432) return;
    int s  = f >> 15;          // /32768
    int b2 = (f >> 8) & 127;
    int g  = f & 255;
    LSTMIN[f] = OUT1[(size_t)b2 * 6144 + s * 256 + g];
}

__global__ void comb_bias(const float* __restrict__ bih0, const float* __restrict__ bhh0,
                          const float* __restrict__ bih1, const float* __restrict__ bhh1,
                          float* __restrict__ B0, float* __restrict__ B1)
{
    int i = blockIdx.x * blockDim.x + threadIdx.x;
    if (i >= 2048) return;
    B0[i] = bih0[i] + bhh0[i];
    B1[i] = bih1[i] + bhh1[i];
}

__global__ void init_state(const float* __restrict__ h0s, const float* __restrict__ c0s,
                           float* __restrict__ HA, float* __restrict__ Cs)
{
    int i = blockIdx.x * blockDim.x + threadIdx.x;
    if (i >= 32768) return;
    HA[i] = h0s[i];
    Cs[i] = c0s[i];
}

// per-step: reduce 4 split-K partials + XG row, apply LSTM nonlinearities, update c/h
__global__ void lstm_finish(const float* __restrict__ GP, const float* __restrict__ XG,
                            float* __restrict__ Cst, float* __restrict__ Hout,
                            float* __restrict__ HSEQ, int t)
{
    int i = blockIdx.x * blockDim.x + threadIdx.x;
    if (i >= 32768) return;
    int b = i >> 9, h = i & 511;
    size_t gbase = (size_t)b * 2048 + h;
    float gi = 0.0f, gf = 0.0f, gg = 0.0f, go = 0.0f;
#pragma unroll
    for (int z = 0; z < 4; z++) {
        const float* gp = GP + (size_t)z * 131072 + gbase;
        gi += gp[0]; gf += gp[512]; gg += gp[1024]; go += gp[1536];
    }
    const float* xg = XG + (size_t)(b * 24 + t) * 2048 + h;
    gi += xg[0]; gf += xg[512]; gg += xg[1024]; go += xg[1536];
    float c = sigmoidf_(gf) * Cst[i] + sigmoidf_(gi) * tanhf(gg);
    Cst[i] = c;
    float hn = sigmoidf_(go) * tanhf(c);
    Hout[i] = hn;
    HSEQ[(size_t)(b * 24 + t) * 512 + h] = hn;
}

// pred = hseq[:, -12:, :] @ lfc_W^T + lfc_b -> NF[:, 0:1536]
__global__ void pred_fc(const float* __restrict__ HSEQ1, const float* __restrict__ lfcW,
                        const float* __restrict__ lfcb, float* __restrict__ NF)
{
    __shared__ float hrow[512];
    int b = blockIdx.x / 12;
    int p = blockIdx.x % 12;
    int row = b * 24 + 12 + p;
    int tid = threadIdx.x;  // 128 threads
    *(float4*)(&hrow[tid * 4]) = *(const float4*)(HSEQ1 + (size_t)row * 512 + tid * 4);
    __syncthreads();
    float acc = lfcb[tid];
    const float* wr = lfcW + (size_t)tid * 512;
#pragma unroll 8
    for (int k = 0; k < 512; k++) acc += hrow[k] * wr[k];
    NF[(size_t)b * 2560 + p * 128 + tid] = acc;
}

// NF[:, 1536:2560] = hidden
__global__ void concat_hidden(const float* __restrict__ HID, float* __restrict__ NF)
{
    int i = blockIdx.x * blockDim.x + threadIdx.x;
    if (i >= 65536) return;
    int b = i >> 10, j = i & 1023;
    NF[(size_t)b * 2560 + 1536 + j] = HID[i];
}

// ---------------- host launch sequence ----------------
extern "C" void kernel_launch(void* const* d_in, const int* in_sizes, int n_in,
                              void* d_out, int out_size)
{
    (void)in_sizes; (void)n_in; (void)out_size;
    const float* x     = (const float*)d_in[0];
    const float* adj   = (const float*)d_in[1];
    const float* h0    = (const float*)d_in[2];
    const float* c0    = (const float*)d_in[3];
    const float* fc11W = (const float*)d_in[4];
    const float* fc11b = (const float*)d_in[5];
    const float* fc12W = (const float*)d_in[6];
    const float* fc12b = (const float*)d_in[7];
    const float* fc21W = (const float*)d_in[8];
    const float* fc21b = (const float*)d_in[9];
    const float* fc22W = (const float*)d_in[10];
    const float* fc22b = (const float*)d_in[11];
    const float* gc1W  = (const float*)d_in[12];
    const float* gc1b  = (const float*)d_in[13];
    const float* gc2W  = (const float*)d_in[14];
    const float* gc2b  = (const float*)d_in[15];
    const float* Wih0  = (const float*)d_in[16];
    const float* Whh0  = (const float*)d_in[17];
    const float* bih0  = (const float*)d_in[18];
    const float* bhh0  = (const float*)d_in[19];
    const float* Wih1  = (const float*)d_in[20];
    const float* Whh1  = (const float*)d_in[21];
    const float* bih1  = (const float*)d_in[22];
    const float* bhh1  = (const float*)d_in[23];
    const float* lfcW  = (const float*)d_in[24];
    const float* lfcb  = (const float*)d_in[25];
    const float* fcW   = (const float*)d_in[26];
    const float* fcb   = (const float*)d_in[27];

    float* out = (float*)d_out;          // [64,12,512] = 393216
    float* outAuto = out + 393216;       // [64,24,512] = 786432

    float* Sc;
    cudaGetSymbolAddress((void**)&Sc, g_scratch);
    float* T1     = Sc + OFF_T1;
    float* HID    = Sc + OFF_HID;
    float* T2     = Sc + OFF_T2;
    float* AUTO   = Sc + OFF_AUTO;
    float* NEWX   = Sc + OFF_NEWX;
    float* M1     = Sc + OFF_M1;
    float* H1     = Sc + OFF_H1;
    float* M2     = Sc + OFF_M2;
    float* OUT1   = Sc + OFF_OUT1;
    float* LSTMIN = Sc + OFF_LSTMIN;
    float* XG     = Sc + OFF_XG;
    float* HSEQ0  = Sc + OFF_HSEQ0;
    float* HSEQ1  = Sc + OFF_HSEQ1;
    float* HA     = Sc + OFF_HA;
    float* HB     = Sc + OFF_HB;
    float* Cst    = Sc + OFF_C;
    float* NF     = Sc + OFF_NF;
    float* B0     = Sc + OFF_B0;
    float* B1     = Sc + OFF_B1;
    float* GP     = Sc + OFF_GP;

    // ---- AutoEncoder ----
    gemm64<<<dim3(64, 1, 2), 256>>>(x, fc11W, nullptr, GP, 64, 4096, 12288, 2, 0);
    reduce_bias_act<<<1024, 256>>>(GP, fc11b, T1, 262144, 4096, 2, 1);
    gemm64<<<dim3(16, 1, 8), 256>>>(T1, fc12W, nullptr, GP, 64, 1024, 4096, 8, 0);
    reduce_bias_act<<<256, 256>>>(GP, fc12b, HID, 65536, 1024, 8, 1);
    gemm64<<<dim3(64, 1, 2), 256>>>(HID, fc21W, nullptr, GP, 64, 4096, 1024, 2, 0);
    reduce_bias_act<<<1024, 256>>>(GP, fc21b, T2, 262144, 4096, 2, 1);
    gemm64<<<dim3(192, 1, 1), 256>>>(T2, fc22W, fc22b, AUTO, 64, 12288, 4096, 1, 1);
    ae_post<<<3072, 256>>>(x, AUTO, NEWX, outAuto);

    // ---- GCN (batched over S as flat [3072, *] GEMMs) ----
    gemm64<<<dim3(8, 48, 1), 256>>>(NEWX, adj, nullptr, M1, 3072, 512, 512, 1, 0);
    gemm64<<<dim3(8, 48, 1), 256>>>(M1, gc1W, gc1b, H1, 3072, 512, 512, 1, 1);
    gemm64<<<dim3(8, 48, 1), 256>>>(H1, adj, nullptr, M2, 3072, 512, 512, 1, 0);
    gemm64<<<dim3(4, 48, 1), 256>>>(M2, gc2W, gc2b, OUT1, 3072, 256, 512, 1, 0);
    permute_lstm_in<<<3072, 256>>>(OUT1, LSTMIN);

    // ---- LSTM ----
    comb_bias<<<8, 256>>>(bih0, bhh0, bih1, bhh1, B0, B1);

    // layer 0
    gemm64<<<dim3(32, 24, 1), 256>>>(LSTMIN, Wih0, B0, XG, 1536, 2048, 512, 1, 0);
    init_state<<<128, 256>>>(h0, c0, HA, Cst);
    for (int t = 0; t < 24; t++) {
        float* hin  = (t & 1) ? HB : HA;
        float* hout = (t & 1) ? HA : HB;
        gemm64<<<dim3(32, 1, 4), 256>>>(hin, Whh0, nullptr, GP, 64, 2048, 512, 4, 0);
        lstm_finish<<<128, 256>>>(GP, XG, Cst, hout, HSEQ0, t);
    }
    // layer 1
    gemm64<<<dim3(32, 24, 1), 256>>>(HSEQ0, Wih1, B1, XG, 1536, 2048, 512, 1, 0);
    init_state<<<128, 256>>>(h0 + 32768, c0 + 32768, HA, Cst);
    for (int t = 0; t < 24; t++) {
        float* hin  = (t & 1) ? HB : HA;
        float* hout = (t & 1) ? HA : HB;
        gemm64<<<dim3(32, 1, 4), 256>>>(hin, Whh1, nullptr, GP, 64, 2048, 512, 4, 0);
        lstm_finish<<<128, 256>>>(GP, XG, Cst, hout, HSEQ1, t);
    }

    // ---- head ----
    pred_fc<<<768, 128>>>(HSEQ1, lfcW, lfcb, NF);
    concat_hidden<<<256, 256>>>(HID, NF);
    gemm64<<<dim3(96, 1, 1), 256>>>(NF, fcW, fcb, out, 64, 6144, 2560, 1, 0);
}

// round 2
// speedup vs baseline: 1.7698x; 1.7698x over previous
#include <cuda_runtime.h>
#include <cuda_bf16.h>
#include <math.h>
#include <stdint.h>

// ---------------- scratch layout (single __device__ arena, no allocs) ----------------
constexpr size_t OFF_T1     = 0;                       // 64*4096
constexpr size_t OFF_HID    = OFF_T1     + 262144;     // 64*1024
constexpr size_t OFF_T2     = OFF_HID    + 65536;      // 64*4096
constexpr size_t OFF_AUTO   = OFF_T2     + 262144;     // 64*12288
constexpr size_t OFF_NEWX   = OFF_AUTO   + 786432;     // 128*24*512
constexpr size_t OFF_M1     = OFF_NEWX   + 1572864;    // 3072*512
constexpr size_t OFF_H1     = OFF_M1     + 1572864;    // 3072*512
constexpr size_t OFF_M2     = OFF_H1     + 1572864;    // 3072*512
constexpr size_t OFF_OUT1   = OFF_M2     + 1572864;    // 3072*256
constexpr size_t OFF_LSTMIN = OFF_OUT1   + 786432;     // 64*24*512
constexpr size_t OFF_XG     = OFF_LSTMIN + 786432;     // 1536*2048
constexpr size_t OFF_HSEQ0  = OFF_XG     + 3145728;    // 64*24*512
constexpr size_t OFF_HSEQ1  = OFF_HSEQ0  + 786432;     // 64*24*512
constexpr size_t OFF_HA     = OFF_HSEQ1  + 786432;     // 64*512
constexpr size_t OFF_HB     = OFF_HA     + 32768;      // 64*512
constexpr size_t OFF_C      = OFF_HB     + 32768;      // 64*512
constexpr size_t OFF_NF     = OFF_C      + 32768;      // 64*2560
constexpr size_t OFF_B0     = OFF_NF     + 163840;     // 2048
constexpr size_t OFF_B1     = OFF_B0     + 2048;       // 2048
constexpr size_t OFF_GP     = OFF_B1     + 2048;       // split-K partials (up to 16 x 262144)
constexpr size_t TOTAL_SCRATCH = OFF_GP  + 4194304;

__device__ float g_scratch[TOTAL_SCRATCH];

__device__ __forceinline__ float sigmoidf_(float v) { return 1.0f / (1.0f + expf(-v)); }

// ---------------- bf16x3 tensor-core GEMM ----------------
// C = act(A[M,K] * W[N,K]^T + bias) using mma.sync m16n8k16 bf16 with hi/lo split
// (3 passes: hi*hi + lo*hi + hi*lo) accumulated in fp32. Error ~2^-17.
// Block tile 64(M) x 128(N) x 32(K), 256 threads (8 warps, 2x4 of 32x32).
// Split-K via gridDim.z: raw fp32 partials to C + z*M*N when kchunks > 1.

__device__ __forceinline__ void bsplit(float x, __nv_bfloat16& h, __nv_bfloat16& l) {
    h = __float2bfloat16(x);
    l = __float2bfloat16(x - __bfloat162float(h));
}

__device__ __forceinline__ uint32_t smem_u32(const void* p) {
    return (uint32_t)__cvta_generic_to_shared(p);
}

__device__ __forceinline__ void ldm_x4(uint32_t addr, uint32_t r[4]) {
    asm volatile("ldmatrix.sync.aligned.m8n8.x4.shared.b16 {%0,%1,%2,%3}, [%4];"
                 : "=r"(r[0]), "=r"(r[1]), "=r"(r[2]), "=r"(r[3]) : "r"(addr));
}
__device__ __forceinline__ void ldm_x2(uint32_t addr, uint32_t r[2]) {
    asm volatile("ldmatrix.sync.aligned.m8n8.x2.shared.b16 {%0,%1}, [%2];"
                 : "=r"(r[0]), "=r"(r[1]) : "r"(addr));
}
__device__ __forceinline__ void mma16816(float d[4], const uint32_t a[4], const uint32_t b[2]) {
    asm volatile("mma.sync.aligned.m16n8k16.row.col.f32.bf16.bf16.f32 "
                 "{%0,%1,%2,%3}, {%4,%5,%6,%7}, {%8,%9}, {%0,%1,%2,%3};"
                 : "+f"(d[0]), "+f"(d[1]), "+f"(d[2]), "+f"(d[3])
                 : "r"(a[0]), "r"(a[1]), "r"(a[2]), "r"(a[3]), "r"(b[0]), "r"(b[1]));
}

constexpr int PAD = 40;  // bf16 row stride: 80 bytes (16B-aligned, conflict-free ldmatrix)

__global__ __launch_bounds__(256) void gemm_bf3(
    const float* __restrict__ A, const float* __restrict__ W,
    const float* __restrict__ bias, float* __restrict__ C,
    int M, int N, int K, int kchunks, int relu)
{
    __shared__ __nv_bfloat16 sAh[64 * PAD], sAl[64 * PAD];
    __shared__ __nv_bfloat16 sWh[128 * PAD], sWl[128 * PAD];

    const int bm = blockIdx.y * 64;
    const int bn = blockIdx.x * 128;
    const int z  = blockIdx.z;
    const int Kc = K / kchunks;
    const int tid  = threadIdx.x;
    const int lane = tid & 31, warp = tid >> 5;
    const int wm = (warp & 1) * 32;   // 2 warps along M
    const int wn = (warp >> 1) * 32;  // 4 warps along N

    float acc[2][4][4];
#pragma unroll
    for (int mi = 0; mi < 2; mi++)
#pragma unroll
        for (int ni = 0; ni < 4; ni++)
#pragma unroll
            for (int e = 0; e < 4; e++) acc[mi][ni][e] = 0.0f;

    const float* Ab = A + (size_t)bm * K + (size_t)z * Kc;
    const float* Wb = W + (size_t)bn * K + (size_t)z * Kc;

    // ldmatrix per-lane offsets
    const int arow = lane & 15, acol8 = (lane >> 4) * 8;      // A: x4 (16x16)
    const int brow = lane & 7,  bcol8 = ((lane >> 3) & 1) * 8; // W: x2 (8 rows x k16)

    for (int kt = 0; kt < Kc; kt += 32) {
        // load + split A tile: 64 x 32 floats, 2 float4 per thread
#pragma unroll
        for (int i = 0; i < 2; i++) {
            int f = tid + i * 256;
            int r = f >> 3, c = (f & 7) * 4;
            float4 v = *(const float4*)(Ab + (size_t)r * K + kt + c);
            bsplit(v.x, sAh[r * PAD + c + 0], sAl[r * PAD + c + 0]);
            bsplit(v.y, sAh[r * PAD + c + 1], sAl[r * PAD + c + 1]);
            bsplit(v.z, sAh[r * PAD + c + 2], sAl[r * PAD + c + 2]);
            bsplit(v.w, sAh[r * PAD + c + 3], sAl[r * PAD + c + 3]);
        }
        // load + split W tile: 128 x 32 floats, 4 float4 per thread
#pragma unroll
        for (int i = 0; i < 4; i++) {
            int f = tid + i * 256;
            int r = f >> 3, c = (f & 7) * 4;
            float4 v = *(const float4*)(Wb + (size_t)r * K + kt + c);
            bsplit(v.x, sWh[r * PAD + c + 0], sWl[r * PAD + c + 0]);
            bsplit(v.y, sWh[r * PAD + c + 1], sWl[r * PAD + c + 1]);
            bsplit(v.z, sWh[r * PAD + c + 2], sWl[r * PAD + c + 2]);
            bsplit(v.w, sWh[r * PAD + c + 3], sWl[r * PAD + c + 3]);
        }
        __syncthreads();

#pragma unroll
        for (int ks = 0; ks < 32; ks += 16) {
            uint32_t ah[2][4], al[2][4], bh[4][2], bl[4][2];
#pragma unroll
            for (int mi = 0; mi < 2; mi++) {
                int r = wm + mi * 16 + arow, c = ks + acol8;
                ldm_x4(smem_u32(&sAh[r * PAD + c]), ah[mi]);
                ldm_x4(smem_u32(&sAl[r * PAD + c]), al[mi]);
            }
#pragma unroll
            for (int ni = 0; ni < 4; ni++) {
                int r = wn + ni * 8 + brow, c = ks + bcol8;
                ldm_x2(smem_u32(&sWh[r * PAD + c]), bh[ni]);
                ldm_x2(smem_u32(&sWl[r * PAD + c]), bl[ni]);
            }
#pragma unroll
            for (int mi = 0; mi < 2; mi++)
#pragma unroll
                for (int ni = 0; ni < 4; ni++) {
                    mma16816(acc[mi][ni], ah[mi], bh[ni]);  // hi*hi
                    mma16816(acc[mi][ni], al[mi], bh[ni]);  // lo*hi
                    mma16816(acc[mi][ni], ah[mi], bl[ni]);  // hi*lo
                }
        }
        __syncthreads();
    }

    float* Cz = C + (size_t)z * ((size_t)M * N);
    const int mr = lane >> 2;           // row within 8-row group
    const int nc = (lane & 3) * 2;      // col pair
#pragma unroll
    for (int mi = 0; mi < 2; mi++)
#pragma unroll
        for (int ni = 0; ni < 4; ni++) {
            int m0 = bm + wm + mi * 16 + mr;
            int n0 = bn + wn + ni * 8 + nc;
            float2 v0 = make_float2(acc[mi][ni][0], acc[mi][ni][1]);
            float2 v1 = make_float2(acc[mi][ni][2], acc[mi][ni][3]);
            if (kchunks == 1) {
                if (bias) {
                    float b0v = bias[n0], b1v = bias[n0 + 1];
                    v0.x += b0v; v0.y += b1v; v1.x += b0v; v1.y += b1v;
                }
                if (relu) {
                    v0.x = fmaxf(v0.x, 0.0f); v0.y = fmaxf(v0.y, 0.0f);
                    v1.x = fmaxf(v1.x, 0.0f); v1.y = fmaxf(v1.y, 0.0f);
                }
            }
            *(float2*)(Cz + (size_t)m0 * N + n0) = v0;
            *(float2*)(Cz + (size_t)(m0 + 8) * N + n0) = v1;
        }
}

// sum split-K partials + bias + optional relu
__global__ void reduce_bias_act(const float* __restrict__ GP, const float* __restrict__ bias,
                                float* __restrict__ out, int total, int N, int kchunks, int relu)
{
    int i = blockIdx.x * blockDim.x + threadIdx.x;
    if (i >= total) return;
    float s = 0.0f;
    for (int z = 0; z < kchunks; z++) s += GP[(size_t)z * total + i];
    if (bias) s += bias[i % N];
    if (relu) s = fmaxf(s, 0.0f);
    out[i] = s;
}

// autooutput -> d_out region; new_x = concat(x, x - auto) along batch
__global__ void ae_post(const float* __restrict__ x, const float* __restrict__ AUTO,
                        float* __restrict__ NEWX, float* __restrict__ outAuto)
{
    int i = blockIdx.x * blockDim.x + threadIdx.x;
    if (i >= 786432) return;
    float xv = x[i], av = AUTO[i];
    NEWX[i] = xv;
    NEWX[786432 + i] = xv - av;
    outAuto[i] = av;
}

// lstm_in flat [64,24,512] from OUT1 [(bfull,s) rows, 256 cols] via [S,2B,G2] C-order view
__global__ void permute_lstm_in(const float* __restrict__ OUT1, float* __restrict__ LSTMIN)
{
    int f = blockIdx.x * blockDim.x + threadIdx.x;
    if (f >= 786432) return;
    int s  = f >> 15;
    int b2 = (f >> 8) & 127;
    int g  = f & 255;
    LSTMIN[f] = OUT1[(size_t)b2 * 6144 + s * 256 + g];
}

__global__ void comb_bias(const float* __restrict__ bih0, const float* __restrict__ bhh0,
                          const float* __restrict__ bih1, const float* __restrict__ bhh1,
                          float* __restrict__ B0, float* __restrict__ B1)
{
    int i = blockIdx.x * blockDim.x + threadIdx.x;
    if (i >= 2048) return;
    B0[i] = bih0[i] + bhh0[i];
    B1[i] = bih1[i] + bhh1[i];
}

__global__ void init_state(const float* __restrict__ h0s, const float* __restrict__ c0s,
                           float* __restrict__ HA, float* __restrict__ Cs)
{
    int i = blockIdx.x * blockDim.x + threadIdx.x;
    if (i >= 32768) return;
    HA[i] = h0s[i];
    Cs[i] = c0s[i];
}

// per-step: reduce 4 split-K partials + XG row, apply LSTM nonlinearities, update c/h
__global__ void lstm_finish(const float* __restrict__ GP, const float* __restrict__ XG,
                            float* __restrict__ Cst, float* __restrict__ Hout,
                            float* __restrict__ HSEQ, int t)
{
    int i = blockIdx.x * blockDim.x + threadIdx.x;
    if (i >= 32768) return;
    int b = i >> 9, h = i & 511;
    size_t gbase = (size_t)b * 2048 + h;
    float gi = 0.0f, gf = 0.0f, gg = 0.0f, go = 0.0f;
#pragma unroll
    for (int z = 0; z < 4; z++) {
        const float* gp = GP + (size_t)z * 131072 + gbase;
        gi += gp[0]; gf += gp[512]; gg += gp[1024]; go += gp[1536];
    }
    const float* xg = XG + (size_t)(b * 24 + t) * 2048 + h;
    gi += xg[0]; gf += xg[512]; gg += xg[1024]; go += xg[1536];
    float c = sigmoidf_(gf) * Cst[i] + sigmoidf_(gi) * tanhf(gg);
    Cst[i] = c;
    float hn = sigmoidf_(go) * tanhf(c);
    Hout[i] = hn;
    HSEQ[(size_t)(b * 24 + t) * 512 + h] = hn;
}

// pred = hseq[:, -12:, :] @ lfc_W^T + lfc_b -> NF[:, 0:1536]
__global__ void pred_fc(const float* __restrict__ HSEQ1, const float* __restrict__ lfcW,
                        const float* __restrict__ lfcb, float* __restrict__ NF)
{
    __shared__ float hrow[512];
    int b = blockIdx.x / 12;
    int p = blockIdx.x % 12;
    int row = b * 24 + 12 + p;
    int tid = threadIdx.x;  // 128 threads
    *(float4*)(&hrow[tid * 4]) = *(const float4*)(HSEQ1 + (size_t)row * 512 + tid * 4);
    __syncthreads();
    float acc = lfcb[tid];
    const float* wr = lfcW + (size_t)tid * 512;
#pragma unroll 8
    for (int k = 0; k < 512; k++) acc += hrow[k] * wr[k];
    NF[(size_t)b * 2560 + p * 128 + tid] = acc;
}

// NF[:, 1536:2560] = hidden
__global__ void concat_hidden(const float* __restrict__ HID, float* __restrict__ NF)
{
    int i = blockIdx.x * blockDim.x + threadIdx.x;
    if (i >= 65536) return;
    int b = i >> 10, j = i & 1023;
    NF[(size_t)b * 2560 + 1536 + j] = HID[i];
}

// ---------------- host launch sequence ----------------
extern "C" void kernel_launch(void* const* d_in, const int* in_sizes, int n_in,
                              void* d_out, int out_size)
{
    (void)in_sizes; (void)n_in; (void)out_size;
    const float* x     = (const float*)d_in[0];
    const float* adj   = (const float*)d_in[1];
    const float* h0    = (const float*)d_in[2];
    const float* c0    = (const float*)d_in[3];
    const float* fc11W = (const float*)d_in[4];
    const float* fc11b = (const float*)d_in[5];
    const float* fc12W = (const float*)d_in[6];
    const float* fc12b = (const float*)d_in[7];
    const float* fc21W = (const float*)d_in[8];
    const float* fc21b = (const float*)d_in[9];
    const float* fc22W = (const float*)d_in[10];
    const float* fc22b = (const float*)d_in[11];
    const float* gc1W  = (const float*)d_in[12];
    const float* gc1b  = (const float*)d_in[13];
    const float* gc2W  = (const float*)d_in[14];
    const float* gc2b  = (const float*)d_in[15];
    const float* Wih0  = (const float*)d_in[16];
    const float* Whh0  = (const float*)d_in[17];
    const float* bih0  = (const float*)d_in[18];
    const float* bhh0  = (const float*)d_in[19];
    const float* Wih1  = (const float*)d_in[20];
    const float* Whh1  = (const float*)d_in[21];
    const float* bih1  = (const float*)d_in[22];
    const float* bhh1  = (const float*)d_in[23];
    const float* lfcW  = (const float*)d_in[24];
    const float* lfcb  = (const float*)d_in[25];
    const float* fcW   = (const float*)d_in[26];
    const float* fcb   = (const float*)d_in[27];

    float* out = (float*)d_out;          // [64,12,512] = 393216
    float* outAuto = out + 393216;       // [64,24,512] = 786432

    float* Sc;
    cudaGetSymbolAddress((void**)&Sc, g_scratch);
    float* T1     = Sc + OFF_T1;
    float* HID    = Sc + OFF_HID;
    float* T2     = Sc + OFF_T2;
    float* AUTO   = Sc + OFF_AUTO;
    float* NEWX   = Sc + OFF_NEWX;
    float* M1     = Sc + OFF_M1;
    float* H1     = Sc + OFF_H1;
    float* M2     = Sc + OFF_M2;
    float* OUT1   = Sc + OFF_OUT1;
    float* LSTMIN = Sc + OFF_LSTMIN;
    float* XG     = Sc + OFF_XG;
    float* HSEQ0  = Sc + OFF_HSEQ0;
    float* HSEQ1  = Sc + OFF_HSEQ1;
    float* HA     = Sc + OFF_HA;
    float* HB     = Sc + OFF_HB;
    float* Cst    = Sc + OFF_C;
    float* NF     = Sc + OFF_NF;
    float* B0     = Sc + OFF_B0;
    float* B1     = Sc + OFF_B1;
    float* GP     = Sc + OFF_GP;

    // ---- AutoEncoder ----
    gemm_bf3<<<dim3(32, 1, 16), 256>>>(x, fc11W, nullptr, GP, 64, 4096, 12288, 16, 0);
    reduce_bias_act<<<1024, 256>>>(GP, fc11b, T1, 262144, 4096, 16, 1);
    gemm_bf3<<<dim3(8, 1, 16), 256>>>(T1, fc12W, nullptr, GP, 64, 1024, 4096, 16, 0);
    reduce_bias_act<<<256, 256>>>(GP, fc12b, HID, 65536, 1024, 16, 1);
    gemm_bf3<<<dim3(32, 1, 8), 256>>>(HID, fc21W, nullptr, GP, 64, 4096, 1024, 8, 0);
    reduce_bias_act<<<1024, 256>>>(GP, fc21b, T2, 262144, 4096, 8, 1);
    gemm_bf3<<<dim3(96, 1, 4), 256>>>(T2, fc22W, nullptr, GP, 64, 12288, 4096, 4, 0);
    reduce_bias_act<<<3072, 256>>>(GP, fc22b, AUTO, 786432, 12288, 4, 1);
    ae_post<<<3072, 256>>>(x, AUTO, NEWX, outAuto);

    // ---- GCN (batched over S as flat [3072, *] GEMMs) ----
    gemm_bf3<<<dim3(4, 48, 1), 256>>>(NEWX, adj, nullptr, M1, 3072, 512, 512, 1, 0);
    gemm_bf3<<<dim3(4, 48, 1), 256>>>(M1, gc1W, gc1b, H1, 3072, 512, 512, 1, 1);
    gemm_bf3<<<dim3(4, 48, 1), 256>>>(H1, adj, nullptr, M2, 3072, 512, 512, 1, 0);
    gemm_bf3<<<dim3(2, 48, 1), 256>>>(M2, gc2W, gc2b, OUT1, 3072, 256, 512, 1, 0);
    permute_lstm_in<<<3072, 256>>>(OUT1, LSTMIN);

    // ---- LSTM ----
    comb_bias<<<8, 256>>>(bih0, bhh0, bih1, bhh1, B0, B1);

    // layer 0
    gemm_bf3<<<dim3(16, 24, 1), 256>>>(LSTMIN, Wih0, B0, XG, 1536, 2048, 512, 1, 0);
    init_state<<<128, 256>>>(h0, c0, HA, Cst);
    for (int t = 0; t < 24; t++) {
        float* hin  = (t & 1) ? HB : HA;
        float* hout = (t & 1) ? HA : HB;
        gemm_bf3<<<dim3(16, 1, 4), 256>>>(hin, Whh0, nullptr, GP, 64, 2048, 512, 4, 0);
        lstm_finish<<<128, 256>>>(GP, XG, Cst, hout, HSEQ0, t);
    }
    // layer 1
    gemm_bf3<<<dim3(16, 24, 1), 256>>>(HSEQ0, Wih1, B1, XG, 1536, 2048, 512, 1, 0);
    init_state<<<128, 256>>>(h0 + 32768, c0 + 32768, HA, Cst);
    for (int t = 0; t < 24; t++) {
        float* hin  = (t & 1) ? HB : HA;
        float* hout = (t & 1) ? HA : HB;
        gemm_bf3<<<dim3(16, 1, 4), 256>>>(hin, Whh1, nullptr, GP, 64, 2048, 512, 4, 0);
        lstm_finish<<<128, 256>>>(GP, XG, Cst, hout, HSEQ1, t);
    }

    // ---- head ----
    pred_fc<<<768, 128>>>(HSEQ1, lfcW, lfcb, NF);
    concat_hidden<<<256, 256>>>(HID, NF);
    gemm_bf3<<<dim3(48, 1, 4), 256>>>(NF, fcW, nullptr, GP, 64, 6144, 2560, 4, 0);
    reduce_bias_act<<<1536, 256>>>(GP, fcb, out, 393216, 6144, 4, 0);
}